// round 11
// baseline (speedup 1.0000x reference)
#include <cuda_runtime.h>
#include <cuda_fp16.h>
#include <math.h>
#include <stdint.h>

// ---------------- problem constants (fixed dataset shapes) ----------------
#define N_MAX   20000
#define E0_MAX  320000
#define ET_MAX  (E0_MAX + N_MAX)
#define FIN     128
#define H1      8
#define C1      64
#define D1      512
#define D2      128
#define NGRAPH  256
#define NOUT    2
#define CAP     128
#define NZB     320     // zero-blocks appended to k_out grid

// ---------------- device scratch ----------------
// INVARIANT: g_counts, g_asrc*/g_adst*, g_pooled are ZERO at launch entry.
// They are zero at module load, and every launch re-zeros them after last use
// (agg2 zeros counts; k_out zeros pooled + attention arrays).
__device__ __half g_h1h   [N_MAX * D1];
__device__ __half g_hout1h[N_MAX * D1];
__device__ __half g_h2h   [N_MAX * D2];
__device__ float g_asrc1[N_MAX * H1];
__device__ float g_adst1[N_MAX * H1];
__device__ float g_asrc2[N_MAX];
__device__ float g_adst2[N_MAX];
__device__ int   g_counts[N_MAX];
__device__ int   g_ssrc  [N_MAX * CAP];
__device__ float g_pooled[NGRAPH * D2];

// ---------------- padded count/scatter ----------------
__global__ void k_countscatter(const int* __restrict__ ei, int E0, int ET) {
    int t = blockIdx.x * blockDim.x + threadIdx.x;
    if (t >= ET) return;
    int s, d;
    if (t < E0) { s = ei[t]; d = ei[E0 + t]; }
    else        { s = d = t - E0; }
    int pos = atomicAdd(&g_counts[d], 1);
    if (pos < CAP) g_ssrc[d * CAP + pos] = s;
}

// ---------------- FP16 tensor-core GEMM: C[M,N] = A[M,K] * B[N,K]^T --------
__device__ __forceinline__ uint32_t pack_h2(float lo, float hi) {
    __half2 h = __floats2half2_rn(lo, hi);
    return *(uint32_t*)&h;
}

__device__ __forceinline__ void mma_f16(float* c, const uint32_t* a, const uint32_t* b) {
    asm volatile("mma.sync.aligned.m16n8k16.row.col.f32.f16.f16.f32 "
        "{%0,%1,%2,%3}, {%4,%5,%6,%7}, {%8,%9}, {%0,%1,%2,%3};"
        : "+f"(c[0]), "+f"(c[1]), "+f"(c[2]), "+f"(c[3])
        : "r"(a[0]), "r"(a[1]), "r"(a[2]), "r"(a[3]), "r"(b[0]), "r"(b[1]));
}

// ATTN: 0 none; 1 conv1 (per-head dot, head = blockIdx.y, atomicAdd);
//       2 conv2 (full-row dot, atomicAdd).  AHALF=1: A is fp16.
template<int ATTN, int AHALF>
__global__ void __launch_bounds__(256)
k_gemm(const void* __restrict__ Av, const float* __restrict__ B,
       __half* __restrict__ C, int M, int N, int K,
       const float* __restrict__ att_s, const float* __restrict__ att_d) {
    __shared__ uint32_t As_u[128 * 16];
    __shared__ uint32_t Bs_u[64 * 16];
    int tid = threadIdx.x;
    int warp = tid >> 5, lane = tid & 31;
    int wm = warp & 3, wn = warp >> 2;
    int grp = lane >> 2, tid4 = lane & 3;
    int bm = blockIdx.x * 128, bn = blockIdx.y * 64;

    const float*  Af = (const float*)Av;
    const __half* Ah = (const __half*)Av;

    float acc[2][4][4];
#pragma unroll
    for (int mt = 0; mt < 2; mt++)
#pragma unroll
        for (int nt = 0; nt < 4; nt++)
#pragma unroll
            for (int r = 0; r < 4; r++) acc[mt][nt][r] = 0.f;

    int arow = tid >> 1, ahalf = tid & 1;
    int brow = tid >> 2, bq = tid & 3;
    bool avalid = (bm + arow) < M;

    float4 pa_f[4];
    uint4  pa_h[2];
    float4 pb[2];

    auto load_tiles = [&](int k0) {
        if (AHALF) {
            if (avalid) {
#pragma unroll
                for (int i = 0; i < 2; i++)
                    pa_h[i] = *(const uint4*)&Ah[(size_t)(bm + arow) * K + k0 + ahalf * 16 + 8 * i];
            } else {
                pa_h[0] = make_uint4(0u, 0u, 0u, 0u);
                pa_h[1] = make_uint4(0u, 0u, 0u, 0u);
            }
        } else {
            if (avalid) {
#pragma unroll
                for (int i = 0; i < 4; i++)
                    pa_f[i] = *(const float4*)&Af[(size_t)(bm + arow) * K + k0 + ahalf * 16 + 4 * i];
            } else {
#pragma unroll
                for (int i = 0; i < 4; i++) pa_f[i] = make_float4(0.f, 0.f, 0.f, 0.f);
            }
        }
#pragma unroll
        for (int i = 0; i < 2; i++)
            pb[i] = *(const float4*)&B[(size_t)(bn + brow) * K + k0 + bq * 8 + 4 * i];
    };

    auto store_tiles = [&]() {
        int asw = (arow & 7) << 1;
        uint32_t au[8];
        if (AHALF) {
            au[0] = pa_h[0].x; au[1] = pa_h[0].y; au[2] = pa_h[0].z; au[3] = pa_h[0].w;
            au[4] = pa_h[1].x; au[5] = pa_h[1].y; au[6] = pa_h[1].z; au[7] = pa_h[1].w;
        } else {
            au[0] = pack_h2(pa_f[0].x, pa_f[0].y); au[1] = pack_h2(pa_f[0].z, pa_f[0].w);
            au[2] = pack_h2(pa_f[1].x, pa_f[1].y); au[3] = pack_h2(pa_f[1].z, pa_f[1].w);
            au[4] = pack_h2(pa_f[2].x, pa_f[2].y); au[5] = pack_h2(pa_f[2].z, pa_f[2].w);
            au[6] = pack_h2(pa_f[3].x, pa_f[3].y); au[7] = pack_h2(pa_f[3].z, pa_f[3].w);
        }
#pragma unroll
        for (int j = 0; j < 4; j++) {
            int cs = (ahalf * 8 + 2 * j) ^ asw;
            *(uint2*)&As_u[arow * 16 + cs] = make_uint2(au[2 * j], au[2 * j + 1]);
        }
        int bsw = (brow & 7) << 1;
        uint32_t bu[4];
        bu[0] = pack_h2(pb[0].x, pb[0].y); bu[1] = pack_h2(pb[0].z, pb[0].w);
        bu[2] = pack_h2(pb[1].x, pb[1].y); bu[3] = pack_h2(pb[1].z, pb[1].w);
#pragma unroll
        for (int j = 0; j < 2; j++) {
            int cs = (bq * 4 + 2 * j) ^ bsw;
            *(uint2*)&Bs_u[brow * 16 + cs] = make_uint2(bu[2 * j], bu[2 * j + 1]);
        }
    };

    load_tiles(0);
    for (int k0 = 0; k0 < K; k0 += 32) {
        store_tiles();
        __syncthreads();
        if (k0 + 32 < K) load_tiles(k0 + 32);

#pragma unroll
        for (int ks = 0; ks < 2; ks++) {
            int j0 = ks * 8 + tid4;
            uint32_t af[2][4];
#pragma unroll
            for (int mt = 0; mt < 2; mt++) {
                int r0 = wm * 32 + mt * 16 + grp;
                int sw = (r0 & 7) << 1;
                af[mt][0] = As_u[r0 * 16 + (j0 ^ sw)];
                af[mt][1] = As_u[(r0 + 8) * 16 + (j0 ^ sw)];
                af[mt][2] = As_u[r0 * 16 + ((j0 + 4) ^ sw)];
                af[mt][3] = As_u[(r0 + 8) * 16 + ((j0 + 4) ^ sw)];
            }
            uint32_t bf[4][2];
#pragma unroll
            for (int nt = 0; nt < 4; nt++) {
                int n0 = wn * 32 + nt * 8 + grp;
                int sw = (n0 & 7) << 1;
                bf[nt][0] = Bs_u[n0 * 16 + (j0 ^ sw)];
                bf[nt][1] = Bs_u[n0 * 16 + ((j0 + 4) ^ sw)];
            }
#pragma unroll
            for (int mt = 0; mt < 2; mt++)
#pragma unroll
                for (int nt = 0; nt < 4; nt++)
                    mma_f16(acc[mt][nt], af[mt], bf[nt]);
        }
        __syncthreads();
    }

#pragma unroll
    for (int mt = 0; mt < 2; mt++) {
        int m0 = bm + wm * 32 + mt * 16 + grp;
#pragma unroll
        for (int nt = 0; nt < 4; nt++) {
            int n0 = bn + wn * 32 + nt * 8 + tid4 * 2;
            if (m0 < M)
                *(__half2*)&C[(size_t)m0 * N + n0] =
                    __floats2half2_rn(acc[mt][nt][0], acc[mt][nt][1]);
            if (m0 + 8 < M)
                *(__half2*)&C[(size_t)(m0 + 8) * N + n0] =
                    __floats2half2_rn(acc[mt][nt][2], acc[mt][nt][3]);
        }
        if (ATTN) {
            // atomics mandatory: the two wn warps hold disjoint column halves
            float sa0 = 0.f, sd0 = 0.f, sa1 = 0.f, sd1 = 0.f;
#pragma unroll
            for (int nt = 0; nt < 4; nt++) {
                int c = bn + wn * 32 + nt * 8 + tid4 * 2;
                float w0s = att_s[c], w1s = att_s[c + 1];
                float w0d = att_d[c], w1d = att_d[c + 1];
                sa0 += acc[mt][nt][0] * w0s + acc[mt][nt][1] * w1s;
                sd0 += acc[mt][nt][0] * w0d + acc[mt][nt][1] * w1d;
                sa1 += acc[mt][nt][2] * w0s + acc[mt][nt][3] * w1s;
                sd1 += acc[mt][nt][2] * w0d + acc[mt][nt][3] * w1d;
            }
#pragma unroll
            for (int o = 1; o < 4; o <<= 1) {
                sa0 += __shfl_xor_sync(0xffffffffu, sa0, o);
                sd0 += __shfl_xor_sync(0xffffffffu, sd0, o);
                sa1 += __shfl_xor_sync(0xffffffffu, sa1, o);
                sd1 += __shfl_xor_sync(0xffffffffu, sd1, o);
            }
            if (tid4 == 0) {
                if (ATTN == 1) {
                    int head = blockIdx.y;
                    if (m0 < M) {
                        atomicAdd(&g_asrc1[m0 * H1 + head], sa0);
                        atomicAdd(&g_adst1[m0 * H1 + head], sd0);
                    }
                    if (m0 + 8 < M) {
                        atomicAdd(&g_asrc1[(m0 + 8) * H1 + head], sa1);
                        atomicAdd(&g_adst1[(m0 + 8) * H1 + head], sd1);
                    }
                } else {
                    if (m0 < M) {
                        atomicAdd(&g_asrc2[m0], sa0);
                        atomicAdd(&g_adst2[m0], sd0);
                    }
                    if (m0 + 8 < M) {
                        atomicAdd(&g_asrc2[m0 + 8], sa1);
                        atomicAdd(&g_adst2[m0 + 8], sd1);
                    }
                }
            }
        }
    }
}

// ---------------- conv1 aggregation: block (128 thr) per destination ----------
// gather phase: 64 threads x uint4 (8 ch) per row; two halves process
// alternate edges; smem combine at the end.
__global__ void __launch_bounds__(128)
k_agg1(const float* __restrict__ bias) {
    __shared__ float s_e[CAP * H1];   // 4 KB
    __shared__ float s_red[D1];       // 2 KB
    int n = blockIdx.x, tid = threadIdx.x;
    int deg = g_counts[n];
    if (deg > CAP) deg = CAP;
    const int* src = g_ssrc + (size_t)n * CAP;

    float ad[H1];
#pragma unroll
    for (int h = 0; h < H1; h++) ad[h] = g_adst1[n * H1 + h];

    for (int i = tid; i < deg; i += 128) {
        int s = src[i];
        const float* as = g_asrc1 + (size_t)s * H1;
#pragma unroll
        for (int h = 0; h < H1; h++) {
            float v = as[h] + ad[h];
            s_e[i * H1 + h] = (v > 0.f) ? v : 0.2f * v;
        }
    }
    __syncthreads();

    {
        int hp = tid >> 4, l16 = tid & 15;
        float m = -1e30f;
        for (int i = l16; i < deg; i += 16) m = fmaxf(m, s_e[i * H1 + hp]);
#pragma unroll
        for (int o = 8; o; o >>= 1) m = fmaxf(m, __shfl_xor_sync(0xffffffffu, m, o, 16));
        float sum = 0.f;
        for (int i = l16; i < deg; i += 16) {
            float ex = __expf(s_e[i * H1 + hp] - m);
            s_e[i * H1 + hp] = ex;
            sum += ex;
        }
#pragma unroll
        for (int o = 8; o; o >>= 1) sum += __shfl_xor_sync(0xffffffffu, sum, o, 16);
        float inv = 1.f / (sum + 1e-16f);
        for (int i = l16; i < deg; i += 16) s_e[i * H1 + hp] *= inv;
    }
    __syncthreads();

    int half = tid >> 6, t64 = tid & 63;
    int base = t64 * 8;
    int hh = t64 >> 3;                 // head = (t64*8)/64
    float acc[8];
#pragma unroll
    for (int j = 0; j < 8; j++) acc[j] = 0.f;

    auto accum = [&](int i) {
        float al = s_e[i * H1 + hh];
        uint4 u = *(const uint4*)(g_h1h + (size_t)src[i] * D1 + base);
        float2 p0 = __half22float2(*(__half2*)&u.x);
        float2 p1 = __half22float2(*(__half2*)&u.y);
        float2 p2 = __half22float2(*(__half2*)&u.z);
        float2 p3 = __half22float2(*(__half2*)&u.w);
        acc[0] = fmaf(al, p0.x, acc[0]); acc[1] = fmaf(al, p0.y, acc[1]);
        acc[2] = fmaf(al, p1.x, acc[2]); acc[3] = fmaf(al, p1.y, acc[3]);
        acc[4] = fmaf(al, p2.x, acc[4]); acc[5] = fmaf(al, p2.y, acc[5]);
        acc[6] = fmaf(al, p3.x, acc[6]); acc[7] = fmaf(al, p3.y, acc[7]);
    };
    int i = half;
    for (; i + 2 < deg; i += 4) { accum(i); accum(i + 2); }
    for (; i < deg; i += 2) accum(i);

    if (half == 1) {
#pragma unroll
        for (int j = 0; j < 8; j += 2)
            *(float2*)&s_red[base + j] = make_float2(acc[j], acc[j + 1]);
    }
    __syncthreads();
    if (half == 0) {
        float r[8];
#pragma unroll
        for (int j = 0; j < 8; j++)
            r[j] = fmaxf(acc[j] + s_red[base + j] + bias[base + j], 0.f);
        uint4 w;
        *(__half2*)&w.x = __floats2half2_rn(r[0], r[1]);
        *(__half2*)&w.y = __floats2half2_rn(r[2], r[3]);
        *(__half2*)&w.z = __floats2half2_rn(r[4], r[5]);
        *(__half2*)&w.w = __floats2half2_rn(r[6], r[7]);
        *(uint4*)(g_hout1h + (size_t)n * D1 + base) = w;
    }
}

// ---------------- conv2 aggregation + fused attention pooling ----------
// gather: 16 lanes x uint4 per row, 2 edges in flight per warp.
__global__ void __launch_bounds__(128)
k_agg2(const float* __restrict__ bias, const int* __restrict__ batch,
       const float* __restrict__ wat, const float* __restrict__ bat,
       const float* __restrict__ wma, const float* __restrict__ bma, int Nn) {
    __shared__ float s_e[4][CAP];
    int wid = threadIdx.x >> 5, lane = threadIdx.x & 31;
    int n = blockIdx.x * 4 + wid;
    if (n >= Nn) return;
    int deg = g_counts[n];
    if (lane == 0) g_counts[n] = 0;     // restore zero-invariant (last reader)
    if (deg > CAP) deg = CAP;
    const int* src = g_ssrc + (size_t)n * CAP;
    float* ebuf = s_e[wid];

    float ad = g_adst2[n];
    for (int i = lane; i < deg; i += 32) {
        float v = g_asrc2[src[i]] + ad;
        ebuf[i] = (v > 0.f) ? v : 0.2f * v;
    }
    __syncwarp();
    float m = -1e30f;
    for (int i = lane; i < deg; i += 32) m = fmaxf(m, ebuf[i]);
#pragma unroll
    for (int o = 16; o; o >>= 1) m = fmaxf(m, __shfl_xor_sync(0xffffffffu, m, o));
    float sum = 0.f;
    for (int i = lane; i < deg; i += 32) {
        float ex = __expf(ebuf[i] - m);
        ebuf[i] = ex;
        sum += ex;
    }
#pragma unroll
    for (int o = 16; o; o >>= 1) sum += __shfl_xor_sync(0xffffffffu, sum, o);
    float inv = 1.f / (sum + 1e-16f);
    for (int i = lane; i < deg; i += 32) ebuf[i] *= inv;
    __syncwarp();

    int q = lane >> 4, l16 = lane & 15;
    int base = l16 * 8;
    float acc[8];
#pragma unroll
    for (int j = 0; j < 8; j++) acc[j] = 0.f;
    for (int i = q; i < deg; i += 2) {
        float al = ebuf[i];
        uint4 u = *(const uint4*)(g_h2h + (size_t)src[i] * D2 + base);
        float2 p0 = __half22float2(*(__half2*)&u.x);
        float2 p1 = __half22float2(*(__half2*)&u.y);
        float2 p2 = __half22float2(*(__half2*)&u.z);
        float2 p3 = __half22float2(*(__half2*)&u.w);
        acc[0] = fmaf(al, p0.x, acc[0]); acc[1] = fmaf(al, p0.y, acc[1]);
        acc[2] = fmaf(al, p1.x, acc[2]); acc[3] = fmaf(al, p1.y, acc[3]);
        acc[4] = fmaf(al, p2.x, acc[4]); acc[5] = fmaf(al, p2.y, acc[5]);
        acc[6] = fmaf(al, p3.x, acc[6]); acc[7] = fmaf(al, p3.y, acc[7]);
    }
#pragma unroll
    for (int j = 0; j < 8; j++)
        acc[j] += __shfl_down_sync(0xffffffffu, acc[j], 16);

    float r[8];
    float sa = 0.f, sm = 0.f;
    if (lane < 16) {
#pragma unroll
        for (int j = 0; j < 8; j++) {
            r[j] = fmaxf(acc[j] + bias[base + j], 0.f);
            sa = fmaf(r[j], wat[base + j], sa);
            sm = fmaf(r[j], wma[base + j], sm);
        }
    }
#pragma unroll
    for (int o = 16; o; o >>= 1) {
        sa += __shfl_xor_sync(0xffffffffu, sa, o);
        sm += __shfl_xor_sync(0xffffffffu, sm, o);
    }
    sa += bat[0];
    sm += bma[0];
    float w = sa * (1.f / (1.f + __expf(-sm)));
    if (lane < 16) {
        int g = batch[n];
        float* p = &g_pooled[g * D2 + base];
#pragma unroll
        for (int j = 0; j < 8; j++) atomicAdd(p + j, w * r[j]);
    }
}

// ---------------- final projection + deferred zeroing ----------------
__global__ void __launch_bounds__(128)
k_out(const float* __restrict__ Wo, const float* __restrict__ bo,
      float* __restrict__ out, int Nn) {
    int b = blockIdx.x;
    int tid = threadIdx.x;
    if (b < NGRAPH) {
        if (tid < 64) {
            int o = tid >> 5, lane = tid & 31;
            float s = 0.f;
#pragma unroll
            for (int i = 0; i < 4; i++) {
                int c = lane + 32 * i;
                s += g_pooled[b * D2 + c] * Wo[o * D2 + c];
            }
#pragma unroll
            for (int off = 16; off; off >>= 1) s += __shfl_xor_sync(0xffffffffu, s, off);
            if (lane == 0) out[b * NOUT + o] = s + bo[o];
        }
        __syncthreads();
        g_pooled[b * D2 + tid] = 0.f;      // D2 == blockDim == 128
    } else {
        int idx = (b - NGRAPH) * 128 + tid;
        int stride = NZB * 128;
        for (int j = idx; j < Nn * H1; j += stride) { g_asrc1[j] = 0.f; g_adst1[j] = 0.f; }
        for (int j = idx; j < Nn; j += stride)      { g_asrc2[j] = 0.f; g_adst2[j] = 0.f; }
    }
}

// ---------------- launcher (multi-stream DAG, 6 nodes) ----------------
extern "C" void kernel_launch(void* const* d_in, const int* in_sizes, int n_in,
                              void* d_out, int out_size) {
    const float* x    = (const float*)d_in[0];
    const int*   ei   = (const int*)  d_in[1];
    const int*   bat_ = (const int*)  d_in[2];
    const float* W1   = (const float*)d_in[3];
    const float* as1  = (const float*)d_in[4];
    const float* ad1  = (const float*)d_in[5];
    const float* b1   = (const float*)d_in[6];
    const float* W2   = (const float*)d_in[7];
    const float* as2  = (const float*)d_in[8];
    const float* ad2  = (const float*)d_in[9];
    const float* b2   = (const float*)d_in[10];
    const float* wat  = (const float*)d_in[11];
    const float* batn = (const float*)d_in[12];
    const float* wma  = (const float*)d_in[13];
    const float* bma  = (const float*)d_in[14];
    const float* Wo   = (const float*)d_in[15];
    const float* bo   = (const float*)d_in[16];
    float* out = (float*)d_out;

    int Nn = in_sizes[0] / FIN;
    int E0 = in_sizes[1] / 2;
    int ET = E0 + Nn;

    static cudaStream_t sB = nullptr;
    static cudaEvent_t ev0 = nullptr, evB = nullptr;
    if (sB == nullptr) {
        cudaStreamCreateWithFlags(&sB, cudaStreamNonBlocking);
        cudaEventCreateWithFlags(&ev0, cudaEventDisableTiming);
        cudaEventCreateWithFlags(&evB, cudaEventDisableTiming);
    }

    __half *p_h1h, *p_h2h, *p_hout1h;
    cudaGetSymbolAddress((void**)&p_h1h, g_h1h);
    cudaGetSymbolAddress((void**)&p_hout1h, g_hout1h);
    cudaGetSymbolAddress((void**)&p_h2h, g_h2h);

    // fork: GEMM1 (conv1 attention epilogue) on sB || adjacency build on main
    cudaEventRecord(ev0, 0);
    cudaStreamWaitEvent(sB, ev0, 0);
    dim3 g1((Nn + 127) / 128, D1 / 64);
    k_gemm<1, 0><<<g1, 256, 0, sB>>>(x, W1, p_h1h, Nn, D1, FIN, as1, ad1);

    k_countscatter<<<(ET + 255) / 256, 256>>>(ei, E0, ET);

    cudaEventRecord(evB, sB);
    cudaStreamWaitEvent(0, evB, 0);

    // serial tail
    k_agg1<<<Nn, 128>>>(b1);
    dim3 g2((Nn + 127) / 128, D2 / 64);
    k_gemm<2, 1><<<g2, 256>>>(p_hout1h, W2, p_h2h, Nn, D2, D1, as2, ad2);
    k_agg2<<<(Nn + 3) / 4, 128>>>(b2, bat_, wat, batn, wma, bma, Nn);
    k_out<<<NGRAPH + NZB, 128>>>(Wo, bo, out, Nn);
}

// round 12
// speedup vs baseline: 1.2371x; 1.2371x over previous
#include <cuda_runtime.h>
#include <cuda_fp16.h>
#include <math.h>
#include <stdint.h>

// ---------------- problem constants (fixed dataset shapes) ----------------
#define N_MAX   20000
#define E0_MAX  320000
#define ET_MAX  (E0_MAX + N_MAX)
#define FIN     128
#define H1      8
#define C1      64
#define D1      512
#define D2      128
#define NGRAPH  256
#define NOUT    2
#define CAP     128

// ---------------- device scratch ----------------
__device__ __half g_h1h   [N_MAX * D1];
__device__ __half g_hout1h[N_MAX * D1];
__device__ __half g_h2h   [N_MAX * D2];
__device__ float g_asrc1[N_MAX * H1];
__device__ float g_adst1[N_MAX * H1];
__device__ float g_asrc2[N_MAX];
__device__ float g_adst2[N_MAX];
__device__ int   g_counts[N_MAX];
__device__ int   g_ssrc  [N_MAX * CAP];
__device__ float g_pooled[NGRAPH * D2];

// ---------------- zero + padded count/scatter ----------------
__global__ void k_zero(int Nn) {
    int i = blockIdx.x * blockDim.x + threadIdx.x;
    if (i < Nn) { g_counts[i] = 0; g_asrc2[i] = 0.f; g_adst2[i] = 0.f; }
    if (i < NGRAPH * D2) g_pooled[i] = 0.f;
    if (i < Nn * H1) { g_asrc1[i] = 0.f; g_adst1[i] = 0.f; }
}

__global__ void k_countscatter(const int* __restrict__ ei, int E0, int ET) {
    int t = blockIdx.x * blockDim.x + threadIdx.x;
    if (t >= ET) return;
    int s, d;
    if (t < E0) { s = ei[t]; d = ei[E0 + t]; }
    else        { s = d = t - E0; }
    int pos = atomicAdd(&g_counts[d], 1);
    if (pos < CAP) g_ssrc[d * CAP + pos] = s;
}

// ---------------- FP16 tensor-core GEMM helpers --------
__device__ __forceinline__ uint32_t pack_h2(float lo, float hi) {
    __half2 h = __floats2half2_rn(lo, hi);
    return *(uint32_t*)&h;
}

__device__ __forceinline__ void mma_f16(float* c, const uint32_t* a, const uint32_t* b) {
    asm volatile("mma.sync.aligned.m16n8k16.row.col.f32.f16.f16.f32 "
        "{%0,%1,%2,%3}, {%4,%5,%6,%7}, {%8,%9}, {%0,%1,%2,%3};"
        : "+f"(c[0]), "+f"(c[1]), "+f"(c[2]), "+f"(c[3])
        : "r"(a[0]), "r"(a[1]), "r"(a[2]), "r"(a[3]), "r"(b[0]), "r"(b[1]));
}

// ---------------- GEMM1: 128x64x32 tile, fp32 A, conv1 attention epilogue ----
__global__ void __launch_bounds__(256)
k_gemm1(const float* __restrict__ A, const float* __restrict__ B,
        __half* __restrict__ C, int M, int N, int K,
        const float* __restrict__ att_s, const float* __restrict__ att_d) {
    __shared__ uint32_t As_u[128 * 16];
    __shared__ uint32_t Bs_u[64 * 16];
    int tid = threadIdx.x;
    int warp = tid >> 5, lane = tid & 31;
    int wm = warp & 3, wn = warp >> 2;
    int grp = lane >> 2, tid4 = lane & 3;
    int bm = blockIdx.x * 128, bn = blockIdx.y * 64;

    float acc[2][4][4];
#pragma unroll
    for (int mt = 0; mt < 2; mt++)
#pragma unroll
        for (int nt = 0; nt < 4; nt++)
#pragma unroll
            for (int r = 0; r < 4; r++) acc[mt][nt][r] = 0.f;

    int arow = tid >> 1, ahalf = tid & 1;
    int brow = tid >> 2, bq = tid & 3;
    bool avalid = (bm + arow) < M;

    float4 pa_f[4];
    float4 pb[2];

    auto load_tiles = [&](int k0) {
        if (avalid) {
#pragma unroll
            for (int i = 0; i < 4; i++)
                pa_f[i] = *(const float4*)&A[(size_t)(bm + arow) * K + k0 + ahalf * 16 + 4 * i];
        } else {
#pragma unroll
            for (int i = 0; i < 4; i++) pa_f[i] = make_float4(0.f, 0.f, 0.f, 0.f);
        }
#pragma unroll
        for (int i = 0; i < 2; i++)
            pb[i] = *(const float4*)&B[(size_t)(bn + brow) * K + k0 + bq * 8 + 4 * i];
    };

    auto store_tiles = [&]() {
        int asw = (arow & 7) << 1;
        uint32_t au[8];
        au[0] = pack_h2(pa_f[0].x, pa_f[0].y); au[1] = pack_h2(pa_f[0].z, pa_f[0].w);
        au[2] = pack_h2(pa_f[1].x, pa_f[1].y); au[3] = pack_h2(pa_f[1].z, pa_f[1].w);
        au[4] = pack_h2(pa_f[2].x, pa_f[2].y); au[5] = pack_h2(pa_f[2].z, pa_f[2].w);
        au[6] = pack_h2(pa_f[3].x, pa_f[3].y); au[7] = pack_h2(pa_f[3].z, pa_f[3].w);
#pragma unroll
        for (int j = 0; j < 4; j++) {
            int cs = (ahalf * 8 + 2 * j) ^ asw;
            *(uint2*)&As_u[arow * 16 + cs] = make_uint2(au[2 * j], au[2 * j + 1]);
        }
        int bsw = (brow & 7) << 1;
        uint32_t bu[4];
        bu[0] = pack_h2(pb[0].x, pb[0].y); bu[1] = pack_h2(pb[0].z, pb[0].w);
        bu[2] = pack_h2(pb[1].x, pb[1].y); bu[3] = pack_h2(pb[1].z, pb[1].w);
#pragma unroll
        for (int j = 0; j < 2; j++) {
            int cs = (bq * 4 + 2 * j) ^ bsw;
            *(uint2*)&Bs_u[brow * 16 + cs] = make_uint2(bu[2 * j], bu[2 * j + 1]);
        }
    };

    load_tiles(0);
    for (int k0 = 0; k0 < K; k0 += 32) {
        store_tiles();
        __syncthreads();
        if (k0 + 32 < K) load_tiles(k0 + 32);

#pragma unroll
        for (int ks = 0; ks < 2; ks++) {
            int j0 = ks * 8 + tid4;
            uint32_t af[2][4];
#pragma unroll
            for (int mt = 0; mt < 2; mt++) {
                int r0 = wm * 32 + mt * 16 + grp;
                int sw = (r0 & 7) << 1;
                af[mt][0] = As_u[r0 * 16 + (j0 ^ sw)];
                af[mt][1] = As_u[(r0 + 8) * 16 + (j0 ^ sw)];
                af[mt][2] = As_u[r0 * 16 + ((j0 + 4) ^ sw)];
                af[mt][3] = As_u[(r0 + 8) * 16 + ((j0 + 4) ^ sw)];
            }
            uint32_t bf[4][2];
#pragma unroll
            for (int nt = 0; nt < 4; nt++) {
                int n0 = wn * 32 + nt * 8 + grp;
                int sw = (n0 & 7) << 1;
                bf[nt][0] = Bs_u[n0 * 16 + (j0 ^ sw)];
                bf[nt][1] = Bs_u[n0 * 16 + ((j0 + 4) ^ sw)];
            }
#pragma unroll
            for (int mt = 0; mt < 2; mt++)
#pragma unroll
                for (int nt = 0; nt < 4; nt++)
                    mma_f16(acc[mt][nt], af[mt], bf[nt]);
        }
        __syncthreads();
    }

#pragma unroll
    for (int mt = 0; mt < 2; mt++) {
        int m0 = bm + wm * 32 + mt * 16 + grp;
#pragma unroll
        for (int nt = 0; nt < 4; nt++) {
            int n0 = bn + wn * 32 + nt * 8 + tid4 * 2;
            if (m0 < M)
                *(__half2*)&C[(size_t)m0 * N + n0] =
                    __floats2half2_rn(acc[mt][nt][0], acc[mt][nt][1]);
            if (m0 + 8 < M)
                *(__half2*)&C[(size_t)(m0 + 8) * N + n0] =
                    __floats2half2_rn(acc[mt][nt][2], acc[mt][nt][3]);
        }
        {   // conv1 attention: head = blockIdx.y; atomics combine the 2 wn warps
            float sa0 = 0.f, sd0 = 0.f, sa1 = 0.f, sd1 = 0.f;
#pragma unroll
            for (int nt = 0; nt < 4; nt++) {
                int c = bn + wn * 32 + nt * 8 + tid4 * 2;
                float w0s = att_s[c], w1s = att_s[c + 1];
                float w0d = att_d[c], w1d = att_d[c + 1];
                sa0 += acc[mt][nt][0] * w0s + acc[mt][nt][1] * w1s;
                sd0 += acc[mt][nt][0] * w0d + acc[mt][nt][1] * w1d;
                sa1 += acc[mt][nt][2] * w0s + acc[mt][nt][3] * w1s;
                sd1 += acc[mt][nt][2] * w0d + acc[mt][nt][3] * w1d;
            }
#pragma unroll
            for (int o = 1; o < 4; o <<= 1) {
                sa0 += __shfl_xor_sync(0xffffffffu, sa0, o);
                sd0 += __shfl_xor_sync(0xffffffffu, sd0, o);
                sa1 += __shfl_xor_sync(0xffffffffu, sa1, o);
                sd1 += __shfl_xor_sync(0xffffffffu, sd1, o);
            }
            if (tid4 == 0) {
                int head = blockIdx.y;
                if (m0 < M) {
                    atomicAdd(&g_asrc1[m0 * H1 + head], sa0);
                    atomicAdd(&g_adst1[m0 * H1 + head], sd0);
                }
                if (m0 + 8 < M) {
                    atomicAdd(&g_asrc1[(m0 + 8) * H1 + head], sa1);
                    atomicAdd(&g_adst1[(m0 + 8) * H1 + head], sd1);
                }
            }
        }
    }
}

// ---------------- GEMM2: 64x64x32 tile, fp16 A, conv2 attention epilogue ----
// 8 warps: wm = warp&1 (rows wm*32..+31), wn = warp>>1 (cols wn*16..+15).
// Warp tile 32x16 = 2x2 m16n8k16; acc 16 regs -> ~60 regs -> 4 blocks/SM.
__global__ void __launch_bounds__(256)
k_gemm2h(const __half* __restrict__ A, const float* __restrict__ B,
         __half* __restrict__ C, int M, int N, int K,
         const float* __restrict__ att_s, const float* __restrict__ att_d) {
    __shared__ uint32_t As_u[64 * 16];
    __shared__ uint32_t Bs_u[64 * 16];
    int tid = threadIdx.x;
    int warp = tid >> 5, lane = tid & 31;
    int wm = warp & 1, wn = warp >> 1;
    int grp = lane >> 2, tid4 = lane & 3;
    int bm = blockIdx.x * 64, bn = blockIdx.y * 64;

    float acc[2][2][4];
#pragma unroll
    for (int mt = 0; mt < 2; mt++)
#pragma unroll
        for (int nt = 0; nt < 2; nt++)
#pragma unroll
            for (int r = 0; r < 4; r++) acc[mt][nt][r] = 0.f;

    int arow = tid >> 2, aq = tid & 3;   // 64 rows x 4 loaders, 8 halves each
    bool avalid = (bm + arow) < M;

    uint4  pa;
    float4 pb[2];

    auto load_tiles = [&](int k0) {
        pa = avalid ? *(const uint4*)&A[(size_t)(bm + arow) * K + k0 + aq * 8]
                    : make_uint4(0u, 0u, 0u, 0u);
#pragma unroll
        for (int i = 0; i < 2; i++)
            pb[i] = *(const float4*)&B[(size_t)(bn + arow) * K + k0 + aq * 8 + 4 * i];
    };

    auto store_tiles = [&]() {
        int sw = (arow & 7) << 1;
#pragma unroll
        for (int j = 0; j < 2; j++) {
            int cs = (aq * 4 + 2 * j) ^ sw;
            uint2 v = (j == 0) ? make_uint2(pa.x, pa.y) : make_uint2(pa.z, pa.w);
            *(uint2*)&As_u[arow * 16 + cs] = v;
        }
        uint32_t bu[4];
        bu[0] = pack_h2(pb[0].x, pb[0].y); bu[1] = pack_h2(pb[0].z, pb[0].w);
        bu[2] = pack_h2(pb[1].x, pb[1].y); bu[3] = pack_h2(pb[1].z, pb[1].w);
#pragma unroll
        for (int j = 0; j < 2; j++) {
            int cs = (aq * 4 + 2 * j) ^ sw;
            *(uint2*)&Bs_u[arow * 16 + cs] = make_uint2(bu[2 * j], bu[2 * j + 1]);
        }
    };

    load_tiles(0);
    for (int k0 = 0; k0 < K; k0 += 32) {
        store_tiles();
        __syncthreads();
        if (k0 + 32 < K) load_tiles(k0 + 32);

#pragma unroll
        for (int ks = 0; ks < 2; ks++) {
            int j0 = ks * 8 + tid4;
            uint32_t af[2][4];
#pragma unroll
            for (int mt = 0; mt < 2; mt++) {
                int r0 = wm * 32 + mt * 16 + grp;
                int sw = (r0 & 7) << 1;
                af[mt][0] = As_u[r0 * 16 + (j0 ^ sw)];
                af[mt][1] = As_u[(r0 + 8) * 16 + (j0 ^ sw)];
                af[mt][2] = As_u[r0 * 16 + ((j0 + 4) ^ sw)];
                af[mt][3] = As_u[(r0 + 8) * 16 + ((j0 + 4) ^ sw)];
            }
            uint32_t bf[2][2];
#pragma unroll
            for (int nt = 0; nt < 2; nt++) {
                int n0 = wn * 16 + nt * 8 + grp;
                int sw = (n0 & 7) << 1;
                bf[nt][0] = Bs_u[n0 * 16 + (j0 ^ sw)];
                bf[nt][1] = Bs_u[n0 * 16 + ((j0 + 4) ^ sw)];
            }
#pragma unroll
            for (int mt = 0; mt < 2; mt++)
#pragma unroll
                for (int nt = 0; nt < 2; nt++)
                    mma_f16(acc[mt][nt], af[mt], bf[nt]);
        }
        __syncthreads();
    }

#pragma unroll
    for (int mt = 0; mt < 2; mt++) {
        int m0 = bm + wm * 32 + mt * 16 + grp;
#pragma unroll
        for (int nt = 0; nt < 2; nt++) {
            int n0 = bn + wn * 16 + nt * 8 + tid4 * 2;
            if (m0 < M)
                *(__half2*)&C[(size_t)m0 * N + n0] =
                    __floats2half2_rn(acc[mt][nt][0], acc[mt][nt][1]);
            if (m0 + 8 < M)
                *(__half2*)&C[(size_t)(m0 + 8) * N + n0] =
                    __floats2half2_rn(acc[mt][nt][2], acc[mt][nt][3]);
        }
        {   // conv2 attention: full-row dot; 4 wn warps combine via atomics
            float sa0 = 0.f, sd0 = 0.f, sa1 = 0.f, sd1 = 0.f;
#pragma unroll
            for (int nt = 0; nt < 2; nt++) {
                int c = bn + wn * 16 + nt * 8 + tid4 * 2;
                float w0s = att_s[c], w1s = att_s[c + 1];
                float w0d = att_d[c], w1d = att_d[c + 1];
                sa0 += acc[mt][nt][0] * w0s + acc[mt][nt][1] * w1s;
                sd0 += acc[mt][nt][0] * w0d + acc[mt][nt][1] * w1d;
                sa1 += acc[mt][nt][2] * w0s + acc[mt][nt][3] * w1s;
                sd1 += acc[mt][nt][2] * w0d + acc[mt][nt][3] * w1d;
            }
#pragma unroll
            for (int o = 1; o < 4; o <<= 1) {
                sa0 += __shfl_xor_sync(0xffffffffu, sa0, o);
                sd0 += __shfl_xor_sync(0xffffffffu, sd0, o);
                sa1 += __shfl_xor_sync(0xffffffffu, sa1, o);
                sd1 += __shfl_xor_sync(0xffffffffu, sd1, o);
            }
            if (tid4 == 0) {
                if (m0 < M) {
                    atomicAdd(&g_asrc2[m0], sa0);
                    atomicAdd(&g_adst2[m0], sd0);
                }
                if (m0 + 8 < M) {
                    atomicAdd(&g_asrc2[m0 + 8], sa1);
                    atomicAdd(&g_adst2[m0 + 8], sd1);
                }
            }
        }
    }
}

// ---------------- conv1 aggregation: block (128 thr) per destination ----------
__global__ void __launch_bounds__(128)
k_agg1(const float* __restrict__ bias) {
    __shared__ float s_e[CAP * H1];
    int n = blockIdx.x, tid = threadIdx.x;
    int deg = g_counts[n];
    if (deg > CAP) deg = CAP;
    const int* src = g_ssrc + (size_t)n * CAP;

    float ad[H1];
#pragma unroll
    for (int h = 0; h < H1; h++) ad[h] = g_adst1[n * H1 + h];

    for (int i = tid; i < deg; i += 128) {
        int s = src[i];
        const float* as = g_asrc1 + (size_t)s * H1;
#pragma unroll
        for (int h = 0; h < H1; h++) {
            float v = as[h] + ad[h];
            s_e[i * H1 + h] = (v > 0.f) ? v : 0.2f * v;
        }
    }
    __syncthreads();

    {
        int hp = tid >> 4, l16 = tid & 15;
        float m = -1e30f;
        for (int i = l16; i < deg; i += 16) m = fmaxf(m, s_e[i * H1 + hp]);
#pragma unroll
        for (int o = 8; o; o >>= 1) m = fmaxf(m, __shfl_xor_sync(0xffffffffu, m, o, 16));
        float sum = 0.f;
        for (int i = l16; i < deg; i += 16) {
            float ex = __expf(s_e[i * H1 + hp] - m);
            s_e[i * H1 + hp] = ex;
            sum += ex;
        }
#pragma unroll
        for (int o = 8; o; o >>= 1) sum += __shfl_xor_sync(0xffffffffu, sum, o, 16);
        float inv = 1.f / (sum + 1e-16f);
        for (int i = l16; i < deg; i += 16) s_e[i * H1 + hp] *= inv;
    }
    __syncthreads();

    int base = tid * 4;
    int hh = base >> 6;
    float a0 = 0.f, a1 = 0.f, a2 = 0.f, a3 = 0.f;
    int i = 0;
    for (; i + 4 <= deg; i += 4) {
        int s0 = src[i], s1 = src[i + 1], s2 = src[i + 2], s3 = src[i + 3];
        float al0 = s_e[(i + 0) * H1 + hh], al1 = s_e[(i + 1) * H1 + hh];
        float al2 = s_e[(i + 2) * H1 + hh], al3 = s_e[(i + 3) * H1 + hh];
        uint2 u0 = *(const uint2*)(g_h1h + (size_t)s0 * D1 + base);
        uint2 u1 = *(const uint2*)(g_h1h + (size_t)s1 * D1 + base);
        uint2 u2 = *(const uint2*)(g_h1h + (size_t)s2 * D1 + base);
        uint2 u3 = *(const uint2*)(g_h1h + (size_t)s3 * D1 + base);
        float2 p0a = __half22float2(*(__half2*)&u0.x), p0b = __half22float2(*(__half2*)&u0.y);
        float2 p1a = __half22float2(*(__half2*)&u1.x), p1b = __half22float2(*(__half2*)&u1.y);
        float2 p2a = __half22float2(*(__half2*)&u2.x), p2b = __half22float2(*(__half2*)&u2.y);
        float2 p3a = __half22float2(*(__half2*)&u3.x), p3b = __half22float2(*(__half2*)&u3.y);
        a0 = fmaf(al0, p0a.x, a0); a1 = fmaf(al0, p0a.y, a1);
        a2 = fmaf(al0, p0b.x, a2); a3 = fmaf(al0, p0b.y, a3);
        a0 = fmaf(al1, p1a.x, a0); a1 = fmaf(al1, p1a.y, a1);
        a2 = fmaf(al1, p1b.x, a2); a3 = fmaf(al1, p1b.y, a3);
        a0 = fmaf(al2, p2a.x, a0); a1 = fmaf(al2, p2a.y, a1);
        a2 = fmaf(al2, p2b.x, a2); a3 = fmaf(al2, p2b.y, a3);
        a0 = fmaf(al3, p3a.x, a0); a1 = fmaf(al3, p3a.y, a1);
        a2 = fmaf(al3, p3b.x, a2); a3 = fmaf(al3, p3b.y, a3);
    }
    for (; i < deg; i++) {
        int s0 = src[i];
        float al0 = s_e[i * H1 + hh];
        uint2 u0 = *(const uint2*)(g_h1h + (size_t)s0 * D1 + base);
        float2 p0a = __half22float2(*(__half2*)&u0.x), p0b = __half22float2(*(__half2*)&u0.y);
        a0 = fmaf(al0, p0a.x, a0); a1 = fmaf(al0, p0a.y, a1);
        a2 = fmaf(al0, p0b.x, a2); a3 = fmaf(al0, p0b.y, a3);
    }
    float r0 = fmaxf(a0 + bias[base + 0], 0.f);
    float r1 = fmaxf(a1 + bias[base + 1], 0.f);
    float r2 = fmaxf(a2 + bias[base + 2], 0.f);
    float r3 = fmaxf(a3 + bias[base + 3], 0.f);
    uint2 w;
    *(__half2*)&w.x = __floats2half2_rn(r0, r1);
    *(__half2*)&w.y = __floats2half2_rn(r2, r3);
    *(uint2*)(g_hout1h + (size_t)n * D1 + base) = w;
}

// ---------------- conv2 aggregation + fused attention pooling ----------
__global__ void __launch_bounds__(128)
k_agg2(const float* __restrict__ bias, const int* __restrict__ batch,
       const float* __restrict__ wat, const float* __restrict__ bat,
       const float* __restrict__ wma, const float* __restrict__ bma, int Nn) {
    __shared__ float s_e[4][CAP];
    int wid = threadIdx.x >> 5, lane = threadIdx.x & 31;
    int n = blockIdx.x * 4 + wid;
    if (n >= Nn) return;
    int deg = g_counts[n];
    if (deg > CAP) deg = CAP;
    const int* src = g_ssrc + (size_t)n * CAP;
    float* ebuf = s_e[wid];

    float ad = g_adst2[n];
    for (int i = lane; i < deg; i += 32) {
        float v = g_asrc2[src[i]] + ad;
        ebuf[i] = (v > 0.f) ? v : 0.2f * v;
    }
    __syncwarp();
    float m = -1e30f;
    for (int i = lane; i < deg; i += 32) m = fmaxf(m, ebuf[i]);
#pragma unroll
    for (int o = 16; o; o >>= 1) m = fmaxf(m, __shfl_xor_sync(0xffffffffu, m, o));
    float sum = 0.f;
    for (int i = lane; i < deg; i += 32) {
        float ex = __expf(ebuf[i] - m);
        ebuf[i] = ex;
        sum += ex;
    }
#pragma unroll
    for (int o = 16; o; o >>= 1) sum += __shfl_xor_sync(0xffffffffu, sum, o);
    float inv = 1.f / (sum + 1e-16f);
    for (int i = lane; i < deg; i += 32) ebuf[i] *= inv;
    __syncwarp();

    int base = lane * 4;
    float a0 = 0.f, a1 = 0.f, a2 = 0.f, a3 = 0.f;
    float b0 = 0.f, b1 = 0.f, b2 = 0.f, b3 = 0.f;
    int i = 0;
    for (; i + 2 <= deg; i += 2) {
        float al0 = ebuf[i], al1 = ebuf[i + 1];
        uint2 u0 = *(const uint2*)(g_h2h + (size_t)src[i] * D2 + base);
        uint2 u1 = *(const uint2*)(g_h2h + (size_t)src[i + 1] * D2 + base);
        float2 p00 = __half22float2(*(__half2*)&u0.x);
        float2 p01 = __half22float2(*(__half2*)&u0.y);
        float2 p10 = __half22float2(*(__half2*)&u1.x);
        float2 p11 = __half22float2(*(__half2*)&u1.y);
        a0 = fmaf(al0, p00.x, a0); a1 = fmaf(al0, p00.y, a1);
        a2 = fmaf(al0, p01.x, a2); a3 = fmaf(al0, p01.y, a3);
        b0 = fmaf(al1, p10.x, b0); b1 = fmaf(al1, p10.y, b1);
        b2 = fmaf(al1, p11.x, b2); b3 = fmaf(al1, p11.y, b3);
    }
    if (i < deg) {
        float al0 = ebuf[i];
        uint2 u0 = *(const uint2*)(g_h2h + (size_t)src[i] * D2 + base);
        float2 p00 = __half22float2(*(__half2*)&u0.x);
        float2 p01 = __half22float2(*(__half2*)&u0.y);
        a0 = fmaf(al0, p00.x, a0); a1 = fmaf(al0, p00.y, a1);
        a2 = fmaf(al0, p01.x, a2); a3 = fmaf(al0, p01.y, a3);
    }
    float4 r;
    r.x = fmaxf(a0 + b0 + bias[base + 0], 0.f);
    r.y = fmaxf(a1 + b1 + bias[base + 1], 0.f);
    r.z = fmaxf(a2 + b2 + bias[base + 2], 0.f);
    r.w = fmaxf(a3 + b3 + bias[base + 3], 0.f);

    float4 a = *(const float4*)(wat + base);
    float4 mm = *(const float4*)(wma + base);
    float sa = r.x * a.x + r.y * a.y + r.z * a.z + r.w * a.w;
    float sm = r.x * mm.x + r.y * mm.y + r.z * mm.z + r.w * mm.w;
#pragma unroll
    for (int o = 16; o; o >>= 1) {
        sa += __shfl_xor_sync(0xffffffffu, sa, o);
        sm += __shfl_xor_sync(0xffffffffu, sm, o);
    }
    sa += bat[0];
    sm += bma[0];
    float w = sa * (1.f / (1.f + __expf(-sm)));
    int g = batch[n];
    float* p = &g_pooled[g * D2 + base];
    atomicAdd(p + 0, w * r.x);
    atomicAdd(p + 1, w * r.y);
    atomicAdd(p + 2, w * r.z);
    atomicAdd(p + 3, w * r.w);
}

// ---------------- final projection ----------------
__global__ void __launch_bounds__(64)
k_out(const float* __restrict__ Wo, const float* __restrict__ bo, float* __restrict__ out) {
    int g = blockIdx.x;
    int o = threadIdx.x >> 5, lane = threadIdx.x & 31;
    float s = 0.f;
#pragma unroll
    for (int i = 0; i < 4; i++) {
        int c = lane + 32 * i;
        s += g_pooled[g * D2 + c] * Wo[o * D2 + c];
    }
#pragma unroll
    for (int off = 16; off; off >>= 1) s += __shfl_xor_sync(0xffffffffu, s, off);
    if (lane == 0) out[g * NOUT + o] = s + bo[o];
}

// ---------------- launcher (multi-stream DAG, 7 nodes) ----------------
extern "C" void kernel_launch(void* const* d_in, const int* in_sizes, int n_in,
                              void* d_out, int out_size) {
    const float* x    = (const float*)d_in[0];
    const int*   ei   = (const int*)  d_in[1];
    const int*   bat_ = (const int*)  d_in[2];
    const float* W1   = (const float*)d_in[3];
    const float* as1  = (const float*)d_in[4];
    const float* ad1  = (const float*)d_in[5];
    const float* b1   = (const float*)d_in[6];
    const float* W2   = (const float*)d_in[7];
    const float* as2  = (const float*)d_in[8];
    const float* ad2  = (const float*)d_in[9];
    const float* b2   = (const float*)d_in[10];
    const float* wat  = (const float*)d_in[11];
    const float* batn = (const float*)d_in[12];
    const float* wma  = (const float*)d_in[13];
    const float* bma  = (const float*)d_in[14];
    const float* Wo   = (const float*)d_in[15];
    const float* bo   = (const float*)d_in[16];
    float* out = (float*)d_out;

    int Nn = in_sizes[0] / FIN;
    int E0 = in_sizes[1] / 2;
    int ET = E0 + Nn;

    static cudaStream_t sB = nullptr;
    static cudaEvent_t ev0 = nullptr, evB = nullptr;
    if (sB == nullptr) {
        cudaStreamCreateWithFlags(&sB, cudaStreamNonBlocking);
        cudaEventCreateWithFlags(&ev0, cudaEventDisableTiming);
        cudaEventCreateWithFlags(&evB, cudaEventDisableTiming);
    }

    __half *p_h1h, *p_h2h, *p_hout1h;
    cudaGetSymbolAddress((void**)&p_h1h, g_h1h);
    cudaGetSymbolAddress((void**)&p_hout1h, g_hout1h);
    cudaGetSymbolAddress((void**)&p_h2h, g_h2h);

    int zn = Nn * H1;

    k_zero<<<(zn + 255) / 256, 256>>>(Nn);

    cudaEventRecord(ev0, 0);
    cudaStreamWaitEvent(sB, ev0, 0);
    dim3 g1((Nn + 127) / 128, D1 / 64);
    k_gemm1<<<g1, 256, 0, sB>>>(x, W1, p_h1h, Nn, D1, FIN, as1, ad1);

    k_countscatter<<<(ET + 255) / 256, 256>>>(ei, E0, ET);

    cudaEventRecord(evB, sB);
    cudaStreamWaitEvent(0, evB, 0);

    k_agg1<<<Nn, 128>>>(b1);
    dim3 g2((Nn + 63) / 64, D2 / 64);
    k_gemm2h<<<g2, 256>>>(p_hout1h, W2, p_h2h, Nn, D2, D1, as2, ad2);
    k_agg2<<<(Nn + 3) / 4, 128>>>(b2, bat_, wat, batn, wma, bma, Nn);
    k_out<<<NGRAPH, 64>>>(Wo, bo, out);
}